// round 4
// baseline (speedup 1.0000x reference)
#include <cuda_runtime.h>

// ---------------- problem constants ----------------
#define BATCH   16
#define TLEN    3000
#define FBINS   201
#define NFFT    400
#define HOP     160
#define MFRAMES (BATCH * TLEN)        // 48000
#define KC      201                    // complex K (bins)
#define NPCOLS  201                    // output "pair" columns n = 0..200
#define NPAD    224                    // padded N for tiling (7 * 32)
#define ESTLEN  480240                 // (T-1)*HOP + NFFT
#define CROP    200                    // n_fft/2
#define OUTLEN  479840                 // ESTLEN - 2*CROP

// ---------------- device scratch (static, no allocs) ----------------
__device__ float2 d_G[KC * NPAD];          // folded trig matrix: (coeff*cos*win/400, 2*sin*win/400)
__device__ float  d_win2[NFFT];            // win^2 for the ssw envelope
__device__ float  d_q[MFRAMES * NFFT];     // windowed irfft frames (76.8 MB)

// ---------------- kernel 0: build tables (runs every launch, ~5 us) ----------------
__global__ void build_tables_kernel() {
    const int k = blockIdx.x;          // 0..200
    const int n = threadIdx.x;         // 0..399
    const double PI = 3.14159265358979323846;

    if (n < NPAD) {
        float c = 0.0f, s = 0.0f;
        if (n <= 200) {
            // exact angle via integer mod: cos/sin(2*pi*(k*n mod 400)/400)
            int kn = (k * n) % NFFT;
            double ang = 2.0 * PI * (double)kn / (double)NFFT;
            double win = 0.54 - 0.46 * cos(2.0 * PI * (double)n / (double)NFFT);
            double wsc = win * (1.0 / (double)NFFT);
            bool edge = (k == 0) || (k == 200);
            double coeff = edge ? 1.0 : 2.0;
            c = (float)(coeff * cos(ang) * wsc);
            s = edge ? 0.0f : (float)(2.0 * sin(ang) * wsc);
        }
        d_G[k * NPAD + n] = make_float2(c, s);
    }
    if (k == 0) {
        double win = 0.54 - 0.46 * cos(2.0 * PI * (double)n / (double)NFFT);
        d_win2[n] = (float)(win * win);
    }
}

// ---------------- kernel 1: fused DFT-GEMM with Hermitian pairing ----------------
// q[m][n]     = A - B,   n = 0..200
// q[m][400-n] = A + B,   n = 1..199
// A = sum_k Re[m][k] * G[k][n].x ;  B = sum_k Im[m][k] * G[k][n].y
#define BM 128
#define BN 32
#define BK 16
#define PADA 2   // float2 padding on As rows

__global__ void __launch_bounds__(256)
dft_gemm_kernel(const float* __restrict__ x) {
    __shared__ float2 As[BK][BM + PADA];   // transposed A tile: [k][m]
    __shared__ float2 Bs[BK][BN];          // B tile: [k][n]

    const int tid = threadIdx.x;
    const int m0 = blockIdx.y * BM;
    const int n0 = blockIdx.x * BN;

    const int ty = tid >> 3;   // 0..31 -> 4 M rows each
    const int tx = tid & 7;    // 0..7  -> 4 N cols each

    float accA[4][4] = {};
    float accB[4][4] = {};

    const float2* __restrict__ xf2 = (const float2*)x;   // [frame][bin] complex

    // A-load mapping: 2048 float2 per tile / 256 thr = 8 each (16 rows x 16 cols per pass)
    const int a_r = tid >> 4;          // 0..15 (row within pass)
    const int a_c = tid & 15;          // 0..15 (k within tile)
    // B-load mapping: 512 float2 per tile / 256 thr = 2 each (8 k-rows x 32 n per pass)
    const int b_k = tid >> 5;          // 0..7
    const int b_n = tid & 31;          // 0..31

    for (int kt = 0; kt < 208; kt += BK) {   // 13 tiles cover K=201 (zero-padded)
        // --- load A tile (transposed into smem) ---
        {
            int kg = kt + a_c;
            bool kok = (kg < KC);
            #pragma unroll
            for (int p = 0; p < 8; p++) {
                int row = p * 16 + a_r;
                float2 v = kok ? xf2[(size_t)(m0 + row) * KC + kg] : make_float2(0.f, 0.f);
                As[a_c][row] = v;
            }
        }
        // --- load B tile ---
        {
            #pragma unroll
            for (int p = 0; p < 2; p++) {
                int kk = p * 8 + b_k;
                int kg = kt + kk;
                float2 v = (kg < KC) ? d_G[kg * NPAD + (n0 + b_n)] : make_float2(0.f, 0.f);
                Bs[kk][b_n] = v;
            }
        }
        __syncthreads();

        // --- compute ---
        #pragma unroll
        for (int kk = 0; kk < BK; kk++) {
            float4 a01 = *(const float4*)&As[kk][ty * 4];
            float4 a23 = *(const float4*)&As[kk][ty * 4 + 2];
            float4 b01 = *(const float4*)&Bs[kk][tx * 4];
            float4 b23 = *(const float4*)&Bs[kk][tx * 4 + 2];
            float ax[4] = {a01.x, a01.z, a23.x, a23.z};
            float ay[4] = {a01.y, a01.w, a23.y, a23.w};
            float bx[4] = {b01.x, b01.z, b23.x, b23.z};
            float by[4] = {b01.y, b01.w, b23.y, b23.w};
            #pragma unroll
            for (int i = 0; i < 4; i++) {
                #pragma unroll
                for (int j = 0; j < 4; j++) {
                    accA[i][j] += ax[i] * bx[j];
                    accB[i][j] += ay[i] * by[j];
                }
            }
        }
        __syncthreads();
    }

    // --- epilogue: paired stores q[n] = A-B, q[400-n] = A+B ---
    #pragma unroll
    for (int i = 0; i < 4; i++) {
        int m = m0 + ty * 4 + i;
        float* qrow = d_q + (size_t)m * NFFT;
        #pragma unroll
        for (int j = 0; j < 4; j++) {
            int n = n0 + tx * 4 + j;
            if (n < NPCOLS) {
                float Av = accA[i][j];
                float Bv = accB[i][j];
                qrow[n] = Av - Bv;
                if (n >= 1 && n <= 199) qrow[NFFT - n] = Av + Bv;
            }
        }
    }
}

// ---------------- kernel 2: gather overlap-add + envelope divide + crop ----------------
__global__ void ola_kernel(float* __restrict__ out) {
    int idx = blockIdx.x * blockDim.x + threadIdx.x;
    const int total = BATCH * OUTLEN;
    if (idx >= total) return;

    int b = idx / OUTLEN;
    int m = idx - b * OUTLEN;
    int p = m + CROP;

    int f_hi = p / HOP;
    if (f_hi > TLEN - 1) f_hi = TLEN - 1;
    int f_lo = (p >= (NFFT - HOP)) ? (p - (NFFT - HOP)) / HOP : 0;  // ceil((p-399)/160)

    const float* __restrict__ qb = d_q + (size_t)b * TLEN * NFFT;

    float acc = 0.0f, sw = 0.0f;
    #pragma unroll 3
    for (int f = f_lo; f <= f_hi; f++) {
        int n = p - f * HOP;
        acc += qb[(size_t)f * NFFT + n];
        sw  += d_win2[n];
    }
    out[idx] = (sw > 1e-12f) ? (acc / sw) : acc;
}

// ---------------- launch ----------------
extern "C" void kernel_launch(void* const* d_in, const int* in_sizes, int n_in,
                              void* d_out, int out_size) {
    const float* x = (const float*)d_in[0];
    float* out = (float*)d_out;

    build_tables_kernel<<<KC, NFFT>>>();

    dim3 grid(NPAD / BN, MFRAMES / BM);   // (7, 375)
    dft_gemm_kernel<<<grid, 256>>>(x);

    int total = BATCH * OUTLEN;
    ola_kernel<<<(total + 255) / 256, 256>>>(out);
}

// round 6
// speedup vs baseline: 1.5567x; 1.5567x over previous
#include <cuda_runtime.h>
#include <cuda_bf16.h>
#include <cstdint>

// ---------------- problem constants ----------------
#define BATCH   16
#define TLEN    3000
#define MFRAMES 48000
#define NFFT    400
#define HOP     160
#define KBINS   201
#define CROP    200
#define OUTLEN  479840

// GEMM shape: D1[M,224] = Re[M,624]*C[624,224] ; D2 = Im*S  (split-3 bf16)
#define KPAD    208            // per-phase K pad (13 x 16)
#define KT_TILES 39            // 3 phases x 13
#define APITCH  416            // [hi(208) | lo(208)]
#define NPADD   224            // padded pair-columns
#define BM      64

// smem staging: per stage  A_re 2KB + A_im 2KB + B_c 7KB + B_s 7KB = 18KB
#define STAGE_BYTES 18432
#define OFS_AIM 2048
#define OFS_BC  4096
#define OFS_BS  11264

// ---------------- device scratch ----------------
__device__ __nv_bfloat16 d_Are[(size_t)MFRAMES * APITCH];  // 40 MB
__device__ __nv_bfloat16 d_Aim[(size_t)MFRAMES * APITCH];  // 40 MB
__device__ __nv_bfloat16 d_Bc[(size_t)NPADD * APITCH];     // [n][k] 186 KB
__device__ __nv_bfloat16 d_Bs[(size_t)NPADD * APITCH];
__device__ float         d_win2[NFFT];
__device__ float         d_q[(size_t)MFRAMES * NFFT];      // 76.8 MB

// ---------------- PTX helpers (family-common ISA only) ----------------
__device__ __forceinline__ uint32_t smem_u32(const void* p) {
    uint32_t a;
    asm("{ .reg .u64 t; cvta.to.shared.u64 t, %1; cvt.u32.u64 %0, t; }" : "=r"(a) : "l"(p));
    return a;
}
__device__ __forceinline__ void cp_async16(uint32_t dst, const void* src) {
    asm volatile("cp.async.cg.shared.global [%0], [%1], 16;\n" :: "r"(dst), "l"(src));
}
__device__ __forceinline__ void ldsm_x4(uint32_t& r0, uint32_t& r1, uint32_t& r2, uint32_t& r3, uint32_t a) {
    asm volatile("ldmatrix.sync.aligned.m8n8.x4.shared.b16 {%0,%1,%2,%3}, [%4];"
                 : "=r"(r0), "=r"(r1), "=r"(r2), "=r"(r3) : "r"(a));
}
__device__ __forceinline__ void ldsm_x2(uint32_t& r0, uint32_t& r1, uint32_t a) {
    asm volatile("ldmatrix.sync.aligned.m8n8.x2.shared.b16 {%0,%1}, [%2];"
                 : "=r"(r0), "=r"(r1) : "r"(a));
}
__device__ __forceinline__ void mma_bf16(float* c, const uint32_t* a, const uint32_t* b) {
    asm volatile(
        "mma.sync.aligned.m16n8k16.row.col.f32.bf16.bf16.f32 "
        "{%0,%1,%2,%3}, {%4,%5,%6,%7}, {%8,%9}, {%0,%1,%2,%3};"
        : "+f"(c[0]), "+f"(c[1]), "+f"(c[2]), "+f"(c[3])
        : "r"(a[0]), "r"(a[1]), "r"(a[2]), "r"(a[3]), "r"(b[0]), "r"(b[1]));
}

// ---------------- kernel 0: build B matrices (split bf16) + win^2 ----------------
__global__ void build_B_kernel() {
    const int n = blockIdx.x;          // 0..399
    const int k = threadIdx.x;         // 0..207
    const double PI = 3.14159265358979323846;
    double win = 0.54 - 0.46 * cos(2.0 * PI * (double)n / 400.0);
    if (n < NPADD) {
        double cv = 0.0, sv = 0.0;
        if (k <= 200 && n <= 200) {
            int kn = (k * n) % 400;                       // exact angle
            double ang = 2.0 * PI * (double)kn / 400.0;
            double coeff = (k == 0 || k == 200) ? 1.0 : 2.0;
            double wsc = win * (1.0 / 400.0);
            cv = coeff * cos(ang) * wsc;
            sv = (k == 0 || k == 200) ? 0.0 : 2.0 * sin(ang) * wsc;
        }
        float cf = (float)cv, sf = (float)sv;
        __nv_bfloat16 ch = __float2bfloat16(cf);
        __nv_bfloat16 cl = __float2bfloat16(cf - __bfloat162float(ch));
        __nv_bfloat16 sh = __float2bfloat16(sf);
        __nv_bfloat16 sl = __float2bfloat16(sf - __bfloat162float(sh));
        d_Bc[(size_t)n * APITCH + k]        = ch;
        d_Bc[(size_t)n * APITCH + KPAD + k] = cl;
        d_Bs[(size_t)n * APITCH + k]        = sh;
        d_Bs[(size_t)n * APITCH + KPAD + k] = sl;
    }
    if (k == 0) d_win2[n] = (float)(win * win);
}

// ---------------- kernel 1: split input into hi/lo bf16 ----------------
__global__ void convert_A_kernel(const float2* __restrict__ x) {
    int idx = blockIdx.x * blockDim.x + threadIdx.x;
    int m = idx / KPAD;
    int j = idx - m * KPAD;
    if (m >= MFRAMES) return;
    __nv_bfloat16* re = d_Are + (size_t)m * APITCH;
    __nv_bfloat16* im = d_Aim + (size_t)m * APITCH;
    if (j < KBINS) {
        float2 v = x[(size_t)m * KBINS + j];
        __nv_bfloat16 rh = __float2bfloat16(v.x);
        __nv_bfloat16 ih = __float2bfloat16(v.y);
        re[j]        = rh;
        re[KPAD + j] = __float2bfloat16(v.x - __bfloat162float(rh));
        im[j]        = ih;
        im[KPAD + j] = __float2bfloat16(v.y - __bfloat162float(ih));
    } else {
        __nv_bfloat16 z = __float2bfloat16(0.0f);
        re[j] = z; re[KPAD + j] = z;
        im[j] = z; im[KPAD + j] = z;
    }
}

// ---------------- kernel 2: mma.sync bf16 GEMM (Hermitian-paired) ----------------
__global__ void __launch_bounds__(256, 1)
gemm_kernel() {
    __shared__ char smem[2 * STAGE_BYTES];
    const uint32_t sbase = smem_u32(smem);
    const int tid  = threadIdx.x;
    const int lane = tid & 31;
    const int warp = tid >> 5;
    const int wm = warp >> 2;          // 0..1
    const int wn = warp & 3;           // 0..3
    const int m0 = blockIdx.x * BM;

    float acc1[2][7][4] = {};          // D1 = Re * C
    float acc2[2][7][4] = {};          // D2 = Im * S

    auto stage_load = [&](int kt) {
        int p = kt / 13;
        int r = kt - p * 13;
        int aofs = (p == 1) ? (KPAD + r * 16) : (r * 16);     // [ah | al | ah]
        int bofs = (p == 2) ? (KPAD + r * 16) : (r * 16);     // [bh | bh | bl]
        uint32_t sdst = sbase + (uint32_t)(kt & 1) * STAGE_BYTES;
        #pragma unroll
        for (int i = tid; i < 1152; i += 256) {
            if (i < 256) {
                int mat = i >> 7;                  // 0 re, 1 im
                int row = (i >> 1) & 63;
                int c   = i & 1;
                const __nv_bfloat16* src =
                    (mat ? d_Aim : d_Are) + (size_t)(m0 + row) * APITCH + aofs + c * 8;
                uint32_t dst = sdst + (uint32_t)mat * OFS_AIM + row * 32
                             + ((c * 16) ^ ((row & 4) << 2));
                cp_async16(dst, src);
            } else {
                int b2  = i - 256;
                int mat = b2 / 448;                // 0 cos, 1 sin
                int r2  = b2 - mat * 448;
                int row = r2 >> 1;                 // 0..223
                int c   = r2 & 1;
                const __nv_bfloat16* src =
                    (mat ? d_Bs : d_Bc) + (size_t)row * APITCH + bofs + c * 8;
                uint32_t dst = sdst + OFS_BC + (uint32_t)mat * 7168 + row * 32
                             + ((c * 16) ^ ((row & 4) << 2));
                cp_async16(dst, src);
            }
        }
        asm volatile("cp.async.commit_group;\n" ::: "memory");
    };

    stage_load(0);

    for (int kt = 0; kt < KT_TILES; kt++) {
        __syncthreads();                               // stage (kt+1)&1 free to overwrite
        if (kt + 1 < KT_TILES) stage_load(kt + 1);
        else asm volatile("cp.async.commit_group;\n" ::: "memory");
        asm volatile("cp.async.wait_group 1;\n" ::: "memory");
        __syncthreads();                               // stage kt&1 fully visible

        uint32_t st = sbase + (uint32_t)(kt & 1) * STAGE_BYTES;

        // ---- A fragments (re, im) x (2 m16 tiles) ----
        uint32_t afr[2][2][4];
        #pragma unroll
        for (int mat = 0; mat < 2; mat++) {
            #pragma unroll
            for (int mt = 0; mt < 2; mt++) {
                int rowA = wm * 32 + mt * 16 + (lane & 15);
                uint32_t a = st + (uint32_t)mat * OFS_AIM + rowA * 32
                           + (((lane >> 4) << 4) ^ ((rowA & 4) << 2));
                ldsm_x4(afr[mat][mt][0], afr[mat][mt][1], afr[mat][mt][2], afr[mat][mt][3], a);
            }
        }
        // ---- B fragments (cos, sin) x (7 n8 tiles) ----
        uint32_t bfr[2][7][2];
        #pragma unroll
        for (int mat = 0; mat < 2; mat++) {
            uint32_t bb = st + OFS_BC + (uint32_t)mat * 7168;
            #pragma unroll
            for (int j = 0; j < 3; j++) {              // tiles 2j, 2j+1
                int grp = lane >> 3;
                int rowB = wn * 56 + j * 16 + (grp >> 1) * 8 + (lane & 7);
                uint32_t a = bb + rowB * 32 + (((grp & 1) * 16) ^ ((rowB & 4) << 2));
                ldsm_x4(bfr[mat][2*j][0], bfr[mat][2*j][1],
                        bfr[mat][2*j+1][0], bfr[mat][2*j+1][1], a);
            }
            {                                          // tile 6 (x2)
                int rowB = wn * 56 + 48 + (lane & 7);
                uint32_t a = bb + rowB * 32 + ((((lane >> 3) & 1) * 16) ^ ((rowB & 4) << 2));
                ldsm_x2(bfr[mat][6][0], bfr[mat][6][1], a);
            }
        }
        // ---- 28 HMMAs ----
        #pragma unroll
        for (int mt = 0; mt < 2; mt++) {
            #pragma unroll
            for (int nt = 0; nt < 7; nt++) {
                mma_bf16(acc1[mt][nt], afr[0][mt], bfr[0][nt]);
                mma_bf16(acc2[mt][nt], afr[1][mt], bfr[1][nt]);
            }
        }
    }

    // ---- epilogue: paired stores q[n]=D1-D2, q[400-n]=D1+D2 ----
    #pragma unroll
    for (int mt = 0; mt < 2; mt++) {
        #pragma unroll
        for (int nt = 0; nt < 7; nt++) {
            #pragma unroll
            for (int c = 0; c < 4; c++) {
                int r   = (lane >> 2) + ((c >= 2) ? 8 : 0);
                int col = 2 * (lane & 3) + (c & 1);
                int m = m0 + wm * 32 + mt * 16 + r;
                int n = wn * 56 + nt * 8 + col;
                if (n <= 200) {
                    float d1 = acc1[mt][nt][c];
                    float d2 = acc2[mt][nt][c];
                    float* qrow = d_q + (size_t)m * NFFT;
                    qrow[n] = d1 - d2;
                    if (n >= 1 && n <= 199) qrow[NFFT - n] = d1 + d2;
                }
            }
        }
    }
}

// ---------------- kernel 3: gather overlap-add + envelope divide + crop ----------------
__global__ void ola_kernel(float* __restrict__ out) {
    int idx = blockIdx.x * blockDim.x + threadIdx.x;
    const int total = BATCH * OUTLEN;
    if (idx >= total) return;

    int b = idx / OUTLEN;
    int m = idx - b * OUTLEN;
    int p = m + CROP;

    int f_hi = p / HOP;
    if (f_hi > TLEN - 1) f_hi = TLEN - 1;
    int f_lo = (p >= (NFFT - HOP)) ? (p - (NFFT - HOP)) / HOP : 0;

    const float* __restrict__ qb = d_q + (size_t)b * TLEN * NFFT;

    float acc = 0.0f, sw = 0.0f;
    #pragma unroll 3
    for (int f = f_lo; f <= f_hi; f++) {
        int n = p - f * HOP;
        acc += qb[(size_t)f * NFFT + n];
        sw  += d_win2[n];
    }
    out[idx] = (sw > 1e-12f) ? (acc / sw) : acc;
}

// ---------------- launch ----------------
extern "C" void kernel_launch(void* const* d_in, const int* in_sizes, int n_in,
                              void* d_out, int out_size) {
    const float2* x = (const float2*)d_in[0];
    float* out = (float*)d_out;

    build_B_kernel<<<NFFT, KPAD>>>();
    convert_A_kernel<<<(MFRAMES * KPAD + 255) / 256, 256>>>(x);
    gemm_kernel<<<MFRAMES / BM, 256>>>();
    ola_kernel<<<(BATCH * OUTLEN + 255) / 256, 256>>>(out);
}

// round 7
// speedup vs baseline: 1.6441x; 1.0562x over previous
#include <cuda_runtime.h>
#include <cuda_bf16.h>
#include <cstdint>

// ---------------- problem constants ----------------
#define BATCH   16
#define TLEN    3000
#define MFRAMES 48000
#define NFFT    400
#define HOP     160
#define KBINS   201
#define CROP    200
#define OUTLEN  479840
#define ESTLEN  480240

// GEMM: D1[M,224] = Re[M,672]*C ; D2 = Im*S  (split-3 bf16, 3 phases x KPAD)
#define KPAD    224            // per-phase K pad (7 x 32)
#define APITCH  448            // [hi(224) | lo(224)]
#define NPADD   224
#define BM      64
#define BK      32
#define KT_TILES 21            // 3 phases x 7

// stage: A_re 4KB + A_im 4KB + B_c 14KB + B_s 14KB = 36KB ; 3 stages
#define STAGE_BYTES 36864
#define OFS_AIM 4096
#define OFS_B   8192
#define SMEM_REQ (3 * STAGE_BYTES)

// ---------------- device scratch ----------------
__device__ __nv_bfloat16 d_Are[(size_t)MFRAMES * APITCH];
__device__ __nv_bfloat16 d_Aim[(size_t)MFRAMES * APITCH];
__device__ __nv_bfloat16 d_Bc[(size_t)NPADD * APITCH];
__device__ __nv_bfloat16 d_Bs[(size_t)NPADD * APITCH];
__device__ float         d_win2[NFFT];
__device__ float         d_issw[ESTLEN];
__device__ float         d_q[(size_t)MFRAMES * NFFT];

// ---------------- PTX helpers (family-common ISA) ----------------
__device__ __forceinline__ uint32_t smem_u32(const void* p) {
    uint32_t a;
    asm("{ .reg .u64 t; cvta.to.shared.u64 t, %1; cvt.u32.u64 %0, t; }" : "=r"(a) : "l"(p));
    return a;
}
__device__ __forceinline__ void cp_async16(uint32_t dst, const void* src) {
    asm volatile("cp.async.cg.shared.global [%0], [%1], 16;\n" :: "r"(dst), "l"(src));
}
__device__ __forceinline__ void ldsm_x4(uint32_t& r0, uint32_t& r1, uint32_t& r2, uint32_t& r3, uint32_t a) {
    asm volatile("ldmatrix.sync.aligned.m8n8.x4.shared.b16 {%0,%1,%2,%3}, [%4];"
                 : "=r"(r0), "=r"(r1), "=r"(r2), "=r"(r3) : "r"(a));
}
__device__ __forceinline__ void ldsm_x2(uint32_t& r0, uint32_t& r1, uint32_t a) {
    asm volatile("ldmatrix.sync.aligned.m8n8.x2.shared.b16 {%0,%1}, [%2];"
                 : "=r"(r0), "=r"(r1) : "r"(a));
}
__device__ __forceinline__ void mma_bf16(float* c, const uint32_t* a, const uint32_t* b) {
    asm volatile(
        "mma.sync.aligned.m16n8k16.row.col.f32.bf16.bf16.f32 "
        "{%0,%1,%2,%3}, {%4,%5,%6,%7}, {%8,%9}, {%0,%1,%2,%3};"
        : "+f"(c[0]), "+f"(c[1]), "+f"(c[2]), "+f"(c[3])
        : "r"(a[0]), "r"(a[1]), "r"(a[2]), "r"(a[3]), "r"(b[0]), "r"(b[1]));
}

// ---------------- kernel 0: build B matrices (split bf16) + win^2 ----------------
__global__ void build_B_kernel() {
    const int n = blockIdx.x;          // 0..399
    const int k = threadIdx.x;         // 0..223
    const double PI = 3.14159265358979323846;
    double win = 0.54 - 0.46 * cos(2.0 * PI * (double)n / 400.0);
    if (n < NPADD) {
        double cv = 0.0, sv = 0.0;
        if (k <= 200 && n <= 200) {
            int kn = (k * n) % 400;
            double ang = 2.0 * PI * (double)kn / 400.0;
            double coeff = (k == 0 || k == 200) ? 1.0 : 2.0;
            double wsc = win * (1.0 / 400.0);
            cv = coeff * cos(ang) * wsc;
            sv = (k == 0 || k == 200) ? 0.0 : 2.0 * sin(ang) * wsc;
        }
        float cf = (float)cv, sf = (float)sv;
        __nv_bfloat16 ch = __float2bfloat16(cf);
        __nv_bfloat16 cl = __float2bfloat16(cf - __bfloat162float(ch));
        __nv_bfloat16 sh = __float2bfloat16(sf);
        __nv_bfloat16 sl = __float2bfloat16(sf - __bfloat162float(sh));
        d_Bc[(size_t)n * APITCH + k]        = ch;
        d_Bc[(size_t)n * APITCH + KPAD + k] = cl;
        d_Bs[(size_t)n * APITCH + k]        = sh;
        d_Bs[(size_t)n * APITCH + KPAD + k] = sl;
    }
    if (k == 0) d_win2[n] = (float)(win * win);
}

// ---------------- kernel 1: inverse squared-window envelope ----------------
__global__ void issw_kernel() {
    int p = blockIdx.x * blockDim.x + threadIdx.x;
    if (p >= ESTLEN) return;
    int f_hi = p / HOP;
    if (f_hi > TLEN - 1) f_hi = TLEN - 1;
    int f_lo = (p >= (NFFT - HOP)) ? (p - (NFFT - HOP)) / HOP : 0;
    float sw = 0.0f;
    #pragma unroll 3
    for (int f = f_lo; f <= f_hi; f++) sw += d_win2[p - f * HOP];
    d_issw[p] = (sw > 1e-12f) ? (1.0f / sw) : 1.0f;
}

// ---------------- kernel 2: split input into hi/lo bf16 (vectorized) ----------------
__global__ void convert_A_kernel(const float2* __restrict__ x) {
    int idx = blockIdx.x * blockDim.x + threadIdx.x;   // MFRAMES * 56
    int m = idx / 56;
    int t4 = idx - m * 56;
    if (m >= MFRAMES) return;
    int j = t4 * 4;

    float vr[4], vi[4];
    #pragma unroll
    for (int u = 0; u < 4; u++) {
        if (j + u < KBINS) {
            float2 v = __ldg(&x[(size_t)m * KBINS + j + u]);
            vr[u] = v.x; vi[u] = v.y;
        } else { vr[u] = 0.0f; vi[u] = 0.0f; }
    }
    __nv_bfloat16 rh[4], rl[4], ih[4], il[4];
    #pragma unroll
    for (int u = 0; u < 4; u++) {
        rh[u] = __float2bfloat16(vr[u]);
        rl[u] = __float2bfloat16(vr[u] - __bfloat162float(rh[u]));
        ih[u] = __float2bfloat16(vi[u]);
        il[u] = __float2bfloat16(vi[u] - __bfloat162float(ih[u]));
    }
    size_t base = (size_t)m * APITCH + j;
    *(uint2*)(d_Are + base)        = *(uint2*)rh;
    *(uint2*)(d_Are + base + KPAD) = *(uint2*)rl;
    *(uint2*)(d_Aim + base)        = *(uint2*)ih;
    *(uint2*)(d_Aim + base + KPAD) = *(uint2*)il;
}

// ---------------- kernel 3: mma.sync bf16 GEMM, 3-stage pipeline ----------------
__global__ void __launch_bounds__(256, 1)
gemm_kernel() {
    extern __shared__ char smem[];
    const uint32_t sbase = smem_u32(smem);
    const int tid  = threadIdx.x;
    const int lane = tid & 31;
    const int warp = tid >> 5;
    const int wm = warp >> 2;          // 0..1
    const int wn = warp & 3;           // 0..3
    const int m0 = blockIdx.x * BM;

    float acc1[2][7][4] = {};          // D1 = Re * C
    float acc2[2][7][4] = {};          // D2 = Im * S

    // per-stage layout: A_re[2 panels x 2KB] | A_im | B_c[2 x 7KB] | B_s
    auto stage_load = [&](int kt) {
        int p = kt / 7;
        int r = kt - p * 7;
        int aofs = ((p == 1) ? KPAD : 0) + r * BK;     // [ah | al | ah]
        int bofs = ((p == 2) ? KPAD : 0) + r * BK;     // [bh | bh | bl]
        uint32_t sdst = sbase + (uint32_t)(kt % 3) * STAGE_BYTES;
        #pragma unroll
        for (int t = 0; t < 9; t++) {
            int i = tid + t * 256;                     // 0..2303
            if (i < 512) {                             // A: 2 mats x 2 panels x 64 rows x 2 chunks
                int mat = i >> 8;
                int r2  = i & 255;
                int pan = r2 >> 7;
                int r3  = r2 & 127;
                int row = r3 >> 1;
                int c   = r3 & 1;
                const __nv_bfloat16* src =
                    (mat ? d_Aim : d_Are) + (size_t)(m0 + row) * APITCH + aofs + pan * 16 + c * 8;
                uint32_t dst = sdst + (uint32_t)mat * OFS_AIM + (uint32_t)pan * 2048u
                             + row * 32 + ((c << 4) ^ ((row & 4) << 2));
                cp_async16(dst, src);
            } else {                                   // B: 2 mats x 2 panels x 224 rows x 2 chunks
                int jj  = i - 512;                     // 0..1791
                int mat = (jj >= 896) ? 1 : 0;
                int r2  = jj - mat * 896;
                int pan = (r2 >= 448) ? 1 : 0;
                int r3  = r2 - pan * 448;
                int row = r3 >> 1;
                int c   = r3 & 1;
                const __nv_bfloat16* src =
                    (mat ? d_Bs : d_Bc) + (size_t)row * APITCH + bofs + pan * 16 + c * 8;
                uint32_t dst = sdst + OFS_B + (uint32_t)mat * 14336u + (uint32_t)pan * 7168u
                             + row * 32 + ((c << 4) ^ ((row & 4) << 2));
                cp_async16(dst, src);
            }
        }
    };

    stage_load(0);
    asm volatile("cp.async.commit_group;\n" ::: "memory");
    stage_load(1);
    asm volatile("cp.async.commit_group;\n" ::: "memory");

    for (int kt = 0; kt < KT_TILES; kt++) {
        asm volatile("cp.async.wait_group 1;\n" ::: "memory");   // group kt complete
        __syncthreads();   // (a) stage kt visible to all, (b) compute(kt-1) finished

        if (kt + 2 < KT_TILES) stage_load(kt + 2);               // overwrites stage (kt-1)%3
        asm volatile("cp.async.commit_group;\n" ::: "memory");

        uint32_t st = sbase + (uint32_t)(kt % 3) * STAGE_BYTES;

        #pragma unroll
        for (int kk = 0; kk < 2; kk++) {                         // two k16 panels
            // A fragments
            uint32_t afr[2][2][4];
            #pragma unroll
            for (int mat = 0; mat < 2; mat++) {
                #pragma unroll
                for (int mt = 0; mt < 2; mt++) {
                    int rowA = wm * 32 + mt * 16 + (lane & 15);
                    uint32_t a = st + (uint32_t)mat * OFS_AIM + (uint32_t)kk * 2048u
                               + rowA * 32 + (((lane >> 4) << 4) ^ ((rowA & 4) << 2));
                    ldsm_x4(afr[mat][mt][0], afr[mat][mt][1], afr[mat][mt][2], afr[mat][mt][3], a);
                }
            }
            // B fragments
            uint32_t bfr[2][7][2];
            #pragma unroll
            for (int mat = 0; mat < 2; mat++) {
                uint32_t bb = st + OFS_B + (uint32_t)mat * 14336u + (uint32_t)kk * 7168u;
                #pragma unroll
                for (int jj = 0; jj < 3; jj++) {
                    int grp = lane >> 3;
                    int rowB = wn * 56 + jj * 16 + (grp >> 1) * 8 + (lane & 7);
                    uint32_t a = bb + rowB * 32 + (((grp & 1) << 4) ^ ((rowB & 4) << 2));
                    ldsm_x4(bfr[mat][2*jj][0], bfr[mat][2*jj][1],
                            bfr[mat][2*jj+1][0], bfr[mat][2*jj+1][1], a);
                }
                {
                    int rowB = wn * 56 + 48 + (lane & 7);
                    uint32_t a = bb + rowB * 32 + ((((lane >> 3) & 1) << 4) ^ ((rowB & 4) << 2));
                    ldsm_x2(bfr[mat][6][0], bfr[mat][6][1], a);
                }
            }
            // 28 HMMAs per panel
            #pragma unroll
            for (int mt = 0; mt < 2; mt++) {
                #pragma unroll
                for (int nt = 0; nt < 7; nt++) {
                    mma_bf16(acc1[mt][nt], afr[0][mt], bfr[0][nt]);
                    mma_bf16(acc2[mt][nt], afr[1][mt], bfr[1][nt]);
                }
            }
        }
    }

    // ---- epilogue: paired stores q[n]=D1-D2, q[400-n]=D1+D2 ----
    #pragma unroll
    for (int mt = 0; mt < 2; mt++) {
        #pragma unroll
        for (int nt = 0; nt < 7; nt++) {
            #pragma unroll
            for (int c = 0; c < 4; c++) {
                int r   = (lane >> 2) + ((c >= 2) ? 8 : 0);
                int col = 2 * (lane & 3) + (c & 1);
                int m = m0 + wm * 32 + mt * 16 + r;
                int n = wn * 56 + nt * 8 + col;
                if (n <= 200) {
                    float d1 = acc1[mt][nt][c];
                    float d2 = acc2[mt][nt][c];
                    float* qrow = d_q + (size_t)m * NFFT;
                    qrow[n] = d1 - d2;
                    if (n >= 1 && n <= 199) qrow[NFFT - n] = d1 + d2;
                }
            }
        }
    }
}

// ---------------- kernel 4: gather overlap-add (2D grid, no div) ----------------
__global__ void ola_kernel(float* __restrict__ out) {
    int m = blockIdx.x * blockDim.x + threadIdx.x;
    if (m >= OUTLEN) return;
    int b = blockIdx.y;
    int p = m + CROP;

    int f_hi = p / HOP;
    if (f_hi > TLEN - 1) f_hi = TLEN - 1;
    int f_lo = (p >= (NFFT - HOP)) ? (p - (NFFT - HOP)) / HOP : 0;

    const float* __restrict__ qb = d_q + (size_t)b * TLEN * NFFT;
    float acc = 0.0f;
    #pragma unroll 3
    for (int f = f_lo; f <= f_hi; f++)
        acc += __ldg(&qb[(size_t)f * NFFT + (p - f * HOP)]);

    out[(size_t)b * OUTLEN + m] = acc * __ldg(&d_issw[p]);
}

// ---------------- launch ----------------
extern "C" void kernel_launch(void* const* d_in, const int* in_sizes, int n_in,
                              void* d_out, int out_size) {
    const float2* x = (const float2*)d_in[0];
    float* out = (float*)d_out;

    build_B_kernel<<<NFFT, KPAD>>>();
    issw_kernel<<<(ESTLEN + 255) / 256, 256>>>();
    convert_A_kernel<<<(MFRAMES * 56 + 255) / 256, 256>>>(x);

    static int smem_set = 0;
    if (!smem_set) {
        cudaFuncSetAttribute(gemm_kernel, cudaFuncAttributeMaxDynamicSharedMemorySize, SMEM_REQ);
        smem_set = 1;
    }
    gemm_kernel<<<MFRAMES / BM, 256, SMEM_REQ>>>();

    dim3 ogrid((OUTLEN + 255) / 256, BATCH);
    ola_kernel<<<ogrid, 256>>>(out);
}

// round 8
// speedup vs baseline: 1.6563x; 1.0074x over previous
#include <cuda_runtime.h>
#include <cuda_bf16.h>
#include <cstdint>

// ---------------- problem constants ----------------
#define BATCH   16
#define TLEN    3000
#define MFRAMES 48000
#define NFFT    400
#define HOP     160
#define KBINS   201
#define CROP    200
#define OUTLEN  479840
#define ESTLEN  480240

// GEMM: D1[M,224] = Re[M,672]*C ; D2 = Im*S  (split-3 bf16, 3 phases x KPAD)
#define KPAD    224            // per-phase K pad (7 x 32)
#define APITCH  448            // [hi(224) | lo(224)]
#define NPADD   224
#define BM      64
#define BK      32
#define KT_TILES 21            // 3 phases x 7

// stage: A_re 4KB + A_im 4KB + B_c 14KB + B_s 14KB = 36KB ; 4 stages
#define STAGE_BYTES 36864
#define OFS_AIM 4096
#define OFS_B   8192
#define NSTAGE  4
#define SMEM_REQ (NSTAGE * STAGE_BYTES)

// ---------------- device scratch ----------------
__device__ __nv_bfloat16 d_Are[(size_t)MFRAMES * APITCH];
__device__ __nv_bfloat16 d_Aim[(size_t)MFRAMES * APITCH];
__device__ __nv_bfloat16 d_Bc[(size_t)NPADD * APITCH];
__device__ __nv_bfloat16 d_Bs[(size_t)NPADD * APITCH];
__device__ float         d_win2[NFFT];
__device__ float         d_issw[ESTLEN];
__device__ float         d_q[(size_t)MFRAMES * NFFT];

// ---------------- PTX helpers (family-common ISA) ----------------
__device__ __forceinline__ uint32_t smem_u32(const void* p) {
    uint32_t a;
    asm("{ .reg .u64 t; cvta.to.shared.u64 t, %1; cvt.u32.u64 %0, t; }" : "=r"(a) : "l"(p));
    return a;
}
__device__ __forceinline__ void cp_async16(uint32_t dst, const void* src) {
    asm volatile("cp.async.cg.shared.global [%0], [%1], 16;\n" :: "r"(dst), "l"(src));
}
__device__ __forceinline__ void ldsm_x4(uint32_t& r0, uint32_t& r1, uint32_t& r2, uint32_t& r3, uint32_t a) {
    asm volatile("ldmatrix.sync.aligned.m8n8.x4.shared.b16 {%0,%1,%2,%3}, [%4];"
                 : "=r"(r0), "=r"(r1), "=r"(r2), "=r"(r3) : "r"(a));
}
__device__ __forceinline__ void ldsm_x2(uint32_t& r0, uint32_t& r1, uint32_t a) {
    asm volatile("ldmatrix.sync.aligned.m8n8.x2.shared.b16 {%0,%1}, [%2];"
                 : "=r"(r0), "=r"(r1) : "r"(a));
}
__device__ __forceinline__ void mma_bf16(float* c, const uint32_t* a, const uint32_t* b) {
    asm volatile(
        "mma.sync.aligned.m16n8k16.row.col.f32.bf16.bf16.f32 "
        "{%0,%1,%2,%3}, {%4,%5,%6,%7}, {%8,%9}, {%0,%1,%2,%3};"
        : "+f"(c[0]), "+f"(c[1]), "+f"(c[2]), "+f"(c[3])
        : "r"(a[0]), "r"(a[1]), "r"(a[2]), "r"(a[3]), "r"(b[0]), "r"(b[1]));
}

// ---------------- kernel 0: build B matrices (split bf16) + win^2 ----------------
__global__ void build_B_kernel() {
    const int n = blockIdx.x;          // 0..399
    const int k = threadIdx.x;         // 0..223
    const double PI = 3.14159265358979323846;
    double win = 0.54 - 0.46 * cos(2.0 * PI * (double)n / 400.0);
    if (n < NPADD) {
        double cv = 0.0, sv = 0.0;
        if (k <= 200 && n <= 200) {
            int kn = (k * n) % 400;
            double ang = 2.0 * PI * (double)kn / 400.0;
            double coeff = (k == 0 || k == 200) ? 1.0 : 2.0;
            double wsc = win * (1.0 / 400.0);
            cv = coeff * cos(ang) * wsc;
            sv = (k == 0 || k == 200) ? 0.0 : 2.0 * sin(ang) * wsc;
        }
        float cf = (float)cv, sf = (float)sv;
        __nv_bfloat16 ch = __float2bfloat16(cf);
        __nv_bfloat16 cl = __float2bfloat16(cf - __bfloat162float(ch));
        __nv_bfloat16 sh = __float2bfloat16(sf);
        __nv_bfloat16 sl = __float2bfloat16(sf - __bfloat162float(sh));
        d_Bc[(size_t)n * APITCH + k]        = ch;
        d_Bc[(size_t)n * APITCH + KPAD + k] = cl;
        d_Bs[(size_t)n * APITCH + k]        = sh;
        d_Bs[(size_t)n * APITCH + KPAD + k] = sl;
    }
    if (k == 0) d_win2[n] = (float)(win * win);
}

// ---------------- kernel 1: inverse squared-window envelope ----------------
__global__ void issw_kernel() {
    int p = blockIdx.x * blockDim.x + threadIdx.x;
    if (p >= ESTLEN) return;
    int f_hi = p / HOP;
    if (f_hi > TLEN - 1) f_hi = TLEN - 1;
    int f_lo = (p >= (NFFT - HOP)) ? (p - (NFFT - HOP)) / HOP : 0;
    float sw = 0.0f;
    #pragma unroll 3
    for (int f = f_lo; f <= f_hi; f++) sw += d_win2[p - f * HOP];
    d_issw[p] = (sw > 1e-12f) ? (1.0f / sw) : 1.0f;
}

// ---------------- kernel 2: split input into hi/lo bf16 (vectorized) ----------------
__global__ void convert_A_kernel(const float2* __restrict__ x) {
    int idx = blockIdx.x * blockDim.x + threadIdx.x;   // MFRAMES * 56
    int m = idx / 56;
    int t4 = idx - m * 56;
    if (m >= MFRAMES) return;
    int j = t4 * 4;

    float vr[4], vi[4];
    #pragma unroll
    for (int u = 0; u < 4; u++) {
        if (j + u < KBINS) {
            float2 v = __ldg(&x[(size_t)m * KBINS + j + u]);
            vr[u] = v.x; vi[u] = v.y;
        } else { vr[u] = 0.0f; vi[u] = 0.0f; }
    }
    __nv_bfloat16 rh[4], rl[4], ih[4], il[4];
    #pragma unroll
    for (int u = 0; u < 4; u++) {
        rh[u] = __float2bfloat16(vr[u]);
        rl[u] = __float2bfloat16(vr[u] - __bfloat162float(rh[u]));
        ih[u] = __float2bfloat16(vi[u]);
        il[u] = __float2bfloat16(vi[u] - __bfloat162float(ih[u]));
    }
    size_t base = (size_t)m * APITCH + j;
    *(uint2*)(d_Are + base)        = *(uint2*)rh;
    *(uint2*)(d_Are + base + KPAD) = *(uint2*)rl;
    *(uint2*)(d_Aim + base)        = *(uint2*)ih;
    *(uint2*)(d_Aim + base + KPAD) = *(uint2*)il;
}

// ---------------- kernel 3: mma.sync bf16 GEMM, 512 threads, 4-stage pipeline ----------------
__global__ void __launch_bounds__(512, 1)
gemm_kernel() {
    extern __shared__ char smem[];
    const uint32_t sbase = smem_u32(smem);
    const int tid  = threadIdx.x;
    const int lane = tid & 31;
    const int warp = tid >> 5;         // 0..15
    const int wm = warp >> 2;          // 0..3 (16 M-rows each)
    const int wn = warp & 3;           // 0..3 (56 N-cols each)
    const int m0 = blockIdx.x * BM;

    float acc1[7][4] = {};             // D1 = Re * C
    float acc2[7][4] = {};             // D2 = Im * S

    // per-stage layout: A_re[2 panels x 2KB] | A_im | B_c[2 x 7KB] | B_s
    auto stage_load = [&](int kt) {
        int p = kt / 7;
        int r = kt - p * 7;
        int aofs = ((p == 1) ? KPAD : 0) + r * BK;     // [ah | al | ah]
        int bofs = ((p == 2) ? KPAD : 0) + r * BK;     // [bh | bh | bl]
        uint32_t sdst = sbase + (uint32_t)(kt % NSTAGE) * STAGE_BYTES;
        #pragma unroll
        for (int t = 0; t < 5; t++) {
            int i = tid + t * 512;                     // 0..2303
            if (i >= 2304) break;
            if (i < 512) {                             // A: 2 mats x 2 panels x 64 rows x 2 chunks
                int mat = i >> 8;
                int r2  = i & 255;
                int pan = r2 >> 7;
                int r3  = r2 & 127;
                int row = r3 >> 1;
                int c   = r3 & 1;
                const __nv_bfloat16* src =
                    (mat ? d_Aim : d_Are) + (size_t)(m0 + row) * APITCH + aofs + pan * 16 + c * 8;
                uint32_t dst = sdst + (uint32_t)mat * OFS_AIM + (uint32_t)pan * 2048u
                             + row * 32 + ((c << 4) ^ ((row & 4) << 2));
                cp_async16(dst, src);
            } else {                                   // B: 2 mats x 2 panels x 224 rows x 2 chunks
                int jj  = i - 512;                     // 0..1791
                int mat = (jj >= 896) ? 1 : 0;
                int r2  = jj - mat * 896;
                int pan = (r2 >= 448) ? 1 : 0;
                int r3  = r2 - pan * 448;
                int row = r3 >> 1;
                int c   = r3 & 1;
                const __nv_bfloat16* src =
                    (mat ? d_Bs : d_Bc) + (size_t)row * APITCH + bofs + pan * 16 + c * 8;
                uint32_t dst = sdst + OFS_B + (uint32_t)mat * 14336u + (uint32_t)pan * 7168u
                             + row * 32 + ((c << 4) ^ ((row & 4) << 2));
                cp_async16(dst, src);
            }
        }
    };

    stage_load(0);
    asm volatile("cp.async.commit_group;\n" ::: "memory");
    stage_load(1);
    asm volatile("cp.async.commit_group;\n" ::: "memory");
    stage_load(2);
    asm volatile("cp.async.commit_group;\n" ::: "memory");

    for (int kt = 0; kt < KT_TILES; kt++) {
        asm volatile("cp.async.wait_group 2;\n" ::: "memory");   // group kt complete
        __syncthreads();   // (a) stage kt visible to all, (b) compute(kt-1) finished

        if (kt + 3 < KT_TILES) stage_load(kt + 3);               // overwrites stage (kt-1)%4
        asm volatile("cp.async.commit_group;\n" ::: "memory");

        uint32_t st = sbase + (uint32_t)(kt % NSTAGE) * STAGE_BYTES;

        #pragma unroll
        for (int kk = 0; kk < 2; kk++) {                         // two k16 panels
            // A fragments (re, im), one m16 tile per warp
            uint32_t afr[2][4];
            #pragma unroll
            for (int mat = 0; mat < 2; mat++) {
                int rowA = wm * 16 + (lane & 15);
                uint32_t a = st + (uint32_t)mat * OFS_AIM + (uint32_t)kk * 2048u
                           + rowA * 32 + (((lane >> 4) << 4) ^ ((rowA & 4) << 2));
                ldsm_x4(afr[mat][0], afr[mat][1], afr[mat][2], afr[mat][3], a);
            }
            // B fragments (cos, sin) x 7 n8 tiles
            uint32_t bfr[2][7][2];
            #pragma unroll
            for (int mat = 0; mat < 2; mat++) {
                uint32_t bb = st + OFS_B + (uint32_t)mat * 14336u + (uint32_t)kk * 7168u;
                #pragma unroll
                for (int jj = 0; jj < 3; jj++) {
                    int grp = lane >> 3;
                    int rowB = wn * 56 + jj * 16 + (grp >> 1) * 8 + (lane & 7);
                    uint32_t a = bb + rowB * 32 + (((grp & 1) << 4) ^ ((rowB & 4) << 2));
                    ldsm_x4(bfr[mat][2*jj][0], bfr[mat][2*jj][1],
                            bfr[mat][2*jj+1][0], bfr[mat][2*jj+1][1], a);
                }
                {
                    int rowB = wn * 56 + 48 + (lane & 7);
                    uint32_t a = bb + rowB * 32 + ((((lane >> 3) & 1) << 4) ^ ((rowB & 4) << 2));
                    ldsm_x2(bfr[mat][6][0], bfr[mat][6][1], a);
                }
            }
            // 14 HMMAs per panel (acc1/acc2 chains independent)
            #pragma unroll
            for (int nt = 0; nt < 7; nt++) {
                mma_bf16(acc1[nt], afr[0], bfr[0][nt]);
                mma_bf16(acc2[nt], afr[1], bfr[1][nt]);
            }
        }
    }

    // ---- epilogue: paired stores q[n]=D1-D2, q[400-n]=D1+D2 ----
    #pragma unroll
    for (int nt = 0; nt < 7; nt++) {
        #pragma unroll
        for (int c = 0; c < 4; c++) {
            int r   = (lane >> 2) + ((c >= 2) ? 8 : 0);
            int col = 2 * (lane & 3) + (c & 1);
            int m = m0 + wm * 16 + r;
            int n = wn * 56 + nt * 8 + col;
            if (n <= 200) {
                float d1 = acc1[nt][c];
                float d2 = acc2[nt][c];
                float* qrow = d_q + (size_t)m * NFFT;
                qrow[n] = d1 - d2;
                if (n >= 1 && n <= 199) qrow[NFFT - n] = d1 + d2;
            }
        }
    }
}

// ---------------- kernel 4: gather overlap-add (2D grid, no div) ----------------
__global__ void ola_kernel(float* __restrict__ out) {
    int m = blockIdx.x * blockDim.x + threadIdx.x;
    if (m >= OUTLEN) return;
    int b = blockIdx.y;
    int p = m + CROP;

    int f_hi = p / HOP;
    if (f_hi > TLEN - 1) f_hi = TLEN - 1;
    int f_lo = (p >= (NFFT - HOP)) ? (p - (NFFT - HOP)) / HOP : 0;

    const float* __restrict__ qb = d_q + (size_t)b * TLEN * NFFT;
    float acc = 0.0f;
    #pragma unroll 3
    for (int f = f_lo; f <= f_hi; f++)
        acc += __ldg(&qb[(size_t)f * NFFT + (p - f * HOP)]);

    out[(size_t)b * OUTLEN + m] = acc * __ldg(&d_issw[p]);
}

// ---------------- launch ----------------
extern "C" void kernel_launch(void* const* d_in, const int* in_sizes, int n_in,
                              void* d_out, int out_size) {
    const float2* x = (const float2*)d_in[0];
    float* out = (float*)d_out;

    build_B_kernel<<<NFFT, KPAD>>>();
    issw_kernel<<<(ESTLEN + 255) / 256, 256>>>();
    convert_A_kernel<<<(MFRAMES * 56 + 255) / 256, 256>>>(x);

    static int smem_set = 0;
    if (!smem_set) {
        cudaFuncSetAttribute(gemm_kernel, cudaFuncAttributeMaxDynamicSharedMemorySize, SMEM_REQ);
        smem_set = 1;
    }
    gemm_kernel<<<MFRAMES / BM, 512, SMEM_REQ>>>();

    dim3 ogrid((OUTLEN + 255) / 256, BATCH);
    ola_kernel<<<ogrid, 256>>>(out);
}